// round 15
// baseline (speedup 1.0000x reference)
#include <cuda_runtime.h>
#include <cuda_bf16.h>
#include <math.h>
#include <stdint.h>

// Problem constants
#define BS   4
#define SEQ  2048
#define DIM  1024
#define NH   16
#define DPH  64
#define M_TOT (BS * SEQ)   // 8192

// ---------------------------------------------------------------------------
// Scratch (device globals)
// ---------------------------------------------------------------------------
__device__ __nv_bfloat16 g_ah[(size_t)M_TOT * DIM];
__device__ __nv_bfloat16 g_al[(size_t)M_TOT * DIM];
__device__ __nv_bfloat16 g_wh[(size_t)DIM * DIM];
__device__ __nv_bfloat16 g_wl[(size_t)DIM * DIM];
__device__ __nv_bfloat16 g_qh[(size_t)M_TOT * DIM];
__device__ __nv_bfloat16 g_ql[(size_t)M_TOT * DIM];
__device__ __nv_bfloat16 g_kh[(size_t)M_TOT * DIM];
__device__ __nv_bfloat16 g_kl[(size_t)M_TOT * DIM];
__device__ __nv_bfloat16 g_vh[(size_t)M_TOT * DIM];
__device__ __nv_bfloat16 g_vl[(size_t)M_TOT * DIM];

// ---------------------------------------------------------------------------
// fp32 -> (bf16 hi, bf16 lo) split
// ---------------------------------------------------------------------------
__global__ void __launch_bounds__(256)
split_bf16(const float* __restrict__ x, __nv_bfloat16* __restrict__ hi,
           __nv_bfloat16* __restrict__ lo, int n4)
{
    int i = blockIdx.x * blockDim.x + threadIdx.x;
    if (i >= n4) return;
    float4 v = ((const float4*)x)[i];
    __nv_bfloat16 h0 = __float2bfloat16(v.x);
    __nv_bfloat16 h1 = __float2bfloat16(v.y);
    __nv_bfloat16 h2 = __float2bfloat16(v.z);
    __nv_bfloat16 h3 = __float2bfloat16(v.w);
    __nv_bfloat16 l0 = __float2bfloat16(v.x - __bfloat162float(h0));
    __nv_bfloat16 l1 = __float2bfloat16(v.y - __bfloat162float(h1));
    __nv_bfloat16 l2 = __float2bfloat16(v.z - __bfloat162float(h2));
    __nv_bfloat16 l3 = __float2bfloat16(v.w - __bfloat162float(h3));
    ushort4 hu = make_ushort4(__bfloat16_as_ushort(h0), __bfloat16_as_ushort(h1),
                              __bfloat16_as_ushort(h2), __bfloat16_as_ushort(h3));
    ushort4 lu = make_ushort4(__bfloat16_as_ushort(l0), __bfloat16_as_ushort(l1),
                              __bfloat16_as_ushort(l2), __bfloat16_as_ushort(l3));
    ((ushort4*)hi)[i] = hu;
    ((ushort4*)lo)[i] = lu;
}

// ---------------------------------------------------------------------------
// mma.sync / ldmatrix helpers (sm_80-level PTX)
// ---------------------------------------------------------------------------
static __device__ __forceinline__ uint32_t smem_u32(const void* p) {
    uint32_t a;
    asm("{ .reg .u64 t; cvta.to.shared.u64 t, %1; cvt.u32.u64 %0, t; }"
        : "=r"(a) : "l"(p));
    return a;
}

__device__ __forceinline__ void cp16(uint32_t dst, const void* src) {
    asm volatile("cp.async.cg.shared.global [%0], [%1], 16;" :: "r"(dst), "l"(src));
}
__device__ __forceinline__ void cp_commit() {
    asm volatile("cp.async.commit_group;" ::: "memory");
}
__device__ __forceinline__ void cp_wait1() {
    asm volatile("cp.async.wait_group 1;" ::: "memory");
}
__device__ __forceinline__ void cp_wait0() {
    asm volatile("cp.async.wait_group 0;" ::: "memory");
}

__device__ __forceinline__ void ldsm_x4(uint32_t* r, uint32_t addr) {
    asm volatile("ldmatrix.sync.aligned.m8n8.x4.shared.b16 {%0,%1,%2,%3}, [%4];"
                 : "=r"(r[0]), "=r"(r[1]), "=r"(r[2]), "=r"(r[3]) : "r"(addr));
}
__device__ __forceinline__ void ldsm_x4_t(uint32_t* r, uint32_t addr) {
    asm volatile("ldmatrix.sync.aligned.m8n8.x4.trans.shared.b16 {%0,%1,%2,%3}, [%4];"
                 : "=r"(r[0]), "=r"(r[1]), "=r"(r[2]), "=r"(r[3]) : "r"(addr));
}

__device__ __forceinline__ void mma16816(float* c, const uint32_t* a,
                                         const uint32_t* b) {
    asm volatile(
        "mma.sync.aligned.m16n8k16.row.col.f32.bf16.bf16.f32 "
        "{%0,%1,%2,%3}, {%4,%5,%6,%7}, {%8,%9}, {%0,%1,%2,%3};"
        : "+f"(c[0]), "+f"(c[1]), "+f"(c[2]), "+f"(c[3])
        : "r"(a[0]), "r"(a[1]), "r"(a[2]), "r"(a[3]), "r"(b[0]), "r"(b[1]));
}

__device__ __forceinline__ uint32_t pk2(__nv_bfloat16 a, __nv_bfloat16 b) {
    return (uint32_t)__bfloat16_as_ushort(a) |
           ((uint32_t)__bfloat16_as_ushort(b) << 16);
}

// SW128 swizzle of a byte offset within a 128B-pitch tile
#define SWZ(o) ((o) ^ (((o) >> 3) & 0x70))

// ---------------------------------------------------------------------------
// HMMA split-bf16 GEMM (unchanged from R10 — validated)
// ---------------------------------------------------------------------------
#define GT_STAGE_BYTES 65536
#define GT_OFF_AH 0
#define GT_OFF_AL 16384
#define GT_OFF_WH 32768
#define GT_OFF_WL 49152
#define GT_SMEM_TOTAL (2 * GT_STAGE_BYTES)

__global__ void __launch_bounds__(256)
gemm_tc(const __nv_bfloat16* __restrict__ ah, const __nv_bfloat16* __restrict__ al,
        const __nv_bfloat16* __restrict__ wh, const __nv_bfloat16* __restrict__ wl,
        const float* __restrict__ bias, float* __restrict__ Cf,
        __nv_bfloat16* __restrict__ Ch, __nv_bfloat16* __restrict__ Cl,
        float scale, int mode)
{
    extern __shared__ char smc[];
    const uint32_t sb = smem_u32(smc);
    const int tid  = threadIdx.x;
    const int wid  = tid >> 5;
    const int lane = tid & 31;
    const int m0 = blockIdx.y << 7;
    const int n0 = blockIdx.x << 7;

    const int wm = (wid & 3) * 32;
    const int wn = (wid >> 2) * 64;

    const int r0  = tid >> 3;
    const int seg = tid & 7;
    const __nv_bfloat16* aph = ah + (size_t)(m0 + r0) * DIM + seg * 8;
    const __nv_bfloat16* apl = al + (size_t)(m0 + r0) * DIM + seg * 8;
    const __nv_bfloat16* wph = wh + (size_t)(n0 + r0) * DIM + seg * 8;
    const __nv_bfloat16* wpl = wl + (size_t)(n0 + r0) * DIM + seg * 8;

#define LOAD_CHUNK(chunk, s)                                                   \
    do {                                                                       \
        const uint32_t buf = sb + (s) * GT_STAGE_BYTES;                        \
        const size_t koff = (size_t)(chunk) * 64;                              \
        _Pragma("unroll")                                                      \
        for (int i_ = 0; i_ < 4; i_++) {                                       \
            const uint32_t sw = SWZ((uint32_t)((r0 + 32 * i_) * 128 + seg * 16)); \
            const size_t ro = (size_t)(32 * i_) * DIM + koff;                  \
            cp16(buf + GT_OFF_AH + sw, aph + ro);                              \
            cp16(buf + GT_OFF_AL + sw, apl + ro);                              \
            cp16(buf + GT_OFF_WH + sw, wph + ro);                              \
            cp16(buf + GT_OFF_WL + sw, wpl + ro);                              \
        }                                                                      \
        cp_commit();                                                           \
    } while (0)

    const int a_row   = wm + (lane & 15);
    const int a_half  = (lane >> 4) << 4;
    const uint32_t a_xor   = (uint32_t)((a_row & 7) << 4);
    const uint32_t a_roff0 = (uint32_t)(a_row * 128);
    const uint32_t a_roff1 = a_roff0 + 16 * 128;

    const int b_row  = wn + (lane & 7) + ((lane & 16) >> 1);
    const int b_half = (lane & 8) ? 16 : 0;
    const uint32_t b_xor  = (uint32_t)((b_row & 7) << 4);
    const uint32_t b_roff = (uint32_t)(b_row * 128);

    float acc[2][8][4];
#pragma unroll
    for (int i = 0; i < 2; i++)
#pragma unroll
        for (int j = 0; j < 8; j++)
#pragma unroll
            for (int t = 0; t < 4; t++) acc[i][j][t] = 0.f;

    LOAD_CHUNK(0, 0);
    LOAD_CHUNK(1, 1);

    for (int c = 0; c < 16; c++) {
        const int s = c & 1;
        if (c < 15) cp_wait1(); else cp_wait0();
        __syncthreads();

        const uint32_t buf = sb + s * GT_STAGE_BYTES;
        const uint32_t tah = buf + GT_OFF_AH;
        const uint32_t tal = buf + GT_OFF_AL;
        const uint32_t twh = buf + GT_OFF_WH;
        const uint32_t twl = buf + GT_OFF_WL;

#pragma unroll
        for (int kc = 0; kc < 4; kc++) {
            const uint32_t abyte = (uint32_t)(a_half + kc * 32) ^ a_xor;
            uint32_t ah0[4], ah1[4], al0[4], al1[4];
            ldsm_x4(ah0, tah + a_roff0 + abyte);
            ldsm_x4(ah1, tah + a_roff1 + abyte);
            ldsm_x4(al0, tal + a_roff0 + abyte);
            ldsm_x4(al1, tal + a_roff1 + abyte);

            const uint32_t bbyte = (uint32_t)(b_half + kc * 32) ^ b_xor;
#pragma unroll
            for (int nb = 0; nb < 4; nb++) {
                uint32_t bh[4], bl[4];
                const uint32_t bro = b_roff + (uint32_t)(nb * 16 * 128);
                ldsm_x4(bh, twh + bro + bbyte);
                ldsm_x4(bl, twl + bro + bbyte);
                mma16816(acc[0][2 * nb + 0], ah0, bh + 0);
                mma16816(acc[0][2 * nb + 1], ah0, bh + 2);
                mma16816(acc[1][2 * nb + 0], ah1, bh + 0);
                mma16816(acc[1][2 * nb + 1], ah1, bh + 2);
                mma16816(acc[0][2 * nb + 0], ah0, bl + 0);
                mma16816(acc[0][2 * nb + 1], ah0, bl + 2);
                mma16816(acc[1][2 * nb + 0], ah1, bl + 0);
                mma16816(acc[1][2 * nb + 1], ah1, bl + 2);
                mma16816(acc[0][2 * nb + 0], al0, bh + 0);
                mma16816(acc[0][2 * nb + 1], al0, bh + 2);
                mma16816(acc[1][2 * nb + 0], al1, bh + 0);
                mma16816(acc[1][2 * nb + 1], al1, bh + 2);
            }
        }

        __syncthreads();
        if (c + 2 < 16) LOAD_CHUNK(c + 2, s);
    }

    const int erow = lane >> 2;
    const int ecol = (lane & 3) * 2;
#pragma unroll
    for (int mi = 0; mi < 2; mi++) {
#pragma unroll
        for (int half = 0; half < 2; half++) {
            const int m = m0 + wm + mi * 16 + erow + half * 8;
            const int b = m >> 11;
            const int sx = m & 2047;
#pragma unroll
            for (int ni = 0; ni < 8; ni++) {
                const int n = n0 + wn + ni * 8 + ecol;
                const float2 bv = __ldg((const float2*)(bias + n));
                float2 v;
                v.x = (acc[mi][ni][2 * half + 0] + bv.x) * scale;
                v.y = (acc[mi][ni][2 * half + 1] + bv.y) * scale;
                if (mode == 0) {
                    *(float2*)&Cf[(size_t)m * DIM + n] = v;
                } else {
                    const int h = n >> 6;
                    const int d = n & 63;
                    const size_t idx =
                        ((size_t)((b << 4) + h) * SEQ + sx) * DPH + d;
                    __nv_bfloat16 hx = __float2bfloat16(v.x);
                    __nv_bfloat16 hy = __float2bfloat16(v.y);
                    *(uint32_t*)&Ch[idx] = pk2(hx, hy);
                    *(uint32_t*)&Cl[idx] =
                        pk2(__float2bfloat16(v.x - __bfloat162float(hx)),
                            __float2bfloat16(v.y - __bfloat162float(hy)));
                }
            }
        }
    }
}
#undef LOAD_CHUNK

// ---------------------------------------------------------------------------
// HMMA split-bf16 flash attention, FA2-style:
//  - 8 warps x 16 q-rows (M-only partition): softmax is warp-local (quad shfl)
//  - P stays in registers (S c-frag pairs == P a-frags), no smem round-trip
//  - Q in registers after one-time ldmatrix
//  - 3-stage cp.async KV pipeline, ONE __syncthreads per kv chunk
// ---------------------------------------------------------------------------
#define AT2_QH 0
#define AT2_QL 16384
#define AT2_STAGE(s) (32768 + (s) * 32768)   // KH+0, KL+8192, VH+16384, VL+24576
#define AT2_SMEM (32768 + 3 * 32768)          // 131072 bytes

__global__ void __launch_bounds__(256)
attn_tc(const __nv_bfloat16* __restrict__ qh, const __nv_bfloat16* __restrict__ ql,
        const __nv_bfloat16* __restrict__ kh, const __nv_bfloat16* __restrict__ kl,
        const __nv_bfloat16* __restrict__ vh, const __nv_bfloat16* __restrict__ vl,
        __nv_bfloat16* __restrict__ outh, __nv_bfloat16* __restrict__ outl)
{
    extern __shared__ char smc[];
    const uint32_t sb = smem_u32(smc);
    const int tid  = threadIdx.x;
    const int wid  = tid >> 5;
    const int lane = tid & 31;
    const int wm = wid * 16;                  // warp's 16 q-rows
    const int bh = blockIdx.y;
    const int q0 = blockIdx.x << 7;
    const size_t base = (size_t)bh * SEQ * DPH;

    // ---- cp.async pointers ----
    const int r0  = tid >> 3;   // 0..31
    const int seg = tid & 7;    // 0..7
    const __nv_bfloat16* qhg = qh + base + (size_t)(q0 + r0) * DPH + seg * 8;
    const __nv_bfloat16* qlg = ql + base + (size_t)(q0 + r0) * DPH + seg * 8;
    const __nv_bfloat16* khg = kh + base + (size_t)r0 * DPH + seg * 8;
    const __nv_bfloat16* klg = kl + base + (size_t)r0 * DPH + seg * 8;
    const __nv_bfloat16* vhg = vh + base + (size_t)r0 * DPH + seg * 8;
    const __nv_bfloat16* vlg = vl + base + (size_t)r0 * DPH + seg * 8;
    const uint32_t ldsw = SWZ((uint32_t)(r0 * 128 + seg * 16));
    const uint32_t ldsw2 = SWZ((uint32_t)((r0 + 32) * 128 + seg * 16));

#define AT2_LOADKV(chunk, s)                                                   \
    do {                                                                       \
        const uint32_t st = sb + AT2_STAGE(s);                                 \
        const size_t co = (size_t)(chunk) * 64 * DPH;                          \
        cp16(st + ldsw,          khg + co);                                    \
        cp16(st + ldsw2,         khg + co + 32 * DPH);                         \
        cp16(st + 8192  + ldsw,  klg + co);                                    \
        cp16(st + 8192  + ldsw2, klg + co + 32 * DPH);                         \
        cp16(st + 16384 + ldsw,  vhg + co);                                    \
        cp16(st + 16384 + ldsw2, vhg + co + 32 * DPH);                         \
        cp16(st + 24576 + ldsw,  vlg + co);                                    \
        cp16(st + 24576 + ldsw2, vlg + co + 32 * DPH);                         \
    } while (0)

    // prologue: group 0 = Q + chunk 0; group 1 = chunk 1
#pragma unroll
    for (int i = 0; i < 4; i++) {
        const uint32_t sw = SWZ((uint32_t)((r0 + 32 * i) * 128 + seg * 16));
        cp16(sb + AT2_QH + sw, qhg + (size_t)(32 * i) * DPH);
        cp16(sb + AT2_QL + sw, qlg + (size_t)(32 * i) * DPH);
    }
    AT2_LOADKV(0, 0);
    cp_commit();
    AT2_LOADKV(1, 1);
    cp_commit();

    // ---- ldmatrix lane addressing ----
    const int a_row = wm + (lane & 15);
    const uint32_t a_xor  = (uint32_t)((a_row & 7) << 4);
    const uint32_t a_off  = (uint32_t)(a_row * 128);
    const uint32_t a_half = (uint32_t)((lane >> 4) << 4);

    const int b_rb = (lane & 7) + ((lane & 16) >> 1);       // row within n16 blk
    const uint32_t b_xor  = (uint32_t)((b_rb & 7) << 4);
    const uint32_t b_half = (lane & 8) ? 16u : 0u;

    const int v_kv = lane & 15;
    const int v_d0 = (lane >> 4) << 3;

    // ---- persistent registers ----
    uint32_t qfh[4][4], qfl[4][4];
    float acc_o[8][4];
#pragma unroll
    for (int j = 0; j < 8; j++)
#pragma unroll
        for (int t = 0; t < 4; t++) acc_o[j][t] = 0.f;
    float m0 = -1e30f, m1 = -1e30f, l0 = 0.f, l1 = 0.f;

    for (int c = 0; c < 32; c++) {
        const int s = c - (c / 3) * 3;   // c % 3
        if (c < 31) cp_wait1(); else cp_wait0();
        __syncthreads();

        if (c == 0) {
            // one-time Q -> registers
#pragma unroll
            for (int kc = 0; kc < 4; kc++) {
                const uint32_t ab = (uint32_t)(a_half + kc * 32) ^ a_xor;
                ldsm_x4(qfh[kc], sb + AT2_QH + a_off + ab);
                ldsm_x4(qfl[kc], sb + AT2_QL + a_off + ab);
            }
        }
        if (c < 30) {   // prefetch chunk c+2 into buffer vacated at c-1
            const int s2 = (c + 2) - ((c + 2) / 3) * 3;
            AT2_LOADKV(c + 2, s2);
            cp_commit();
        }

        const uint32_t KH = sb + AT2_STAGE(s);
        const uint32_t KL = KH + 8192;
        const uint32_t VH = KH + 16384;
        const uint32_t VL = KH + 24576;

        // ---- S = Q K^T (3 split terms), 16 x 64 per warp ----
        float acc_s[8][4];
#pragma unroll
        for (int j = 0; j < 8; j++)
#pragma unroll
            for (int t = 0; t < 4; t++) acc_s[j][t] = 0.f;

#pragma unroll
        for (int kc = 0; kc < 4; kc++) {
            const uint32_t bb = (uint32_t)(b_half + kc * 32) ^ b_xor;
#pragma unroll
            for (int nb = 0; nb < 4; nb++) {
                const uint32_t bro = (uint32_t)((nb * 16 + b_rb) * 128);
                uint32_t khr[4], klr[4];
                ldsm_x4(khr, KH + bro + bb);
                ldsm_x4(klr, KL + bro + bb);
                mma16816(acc_s[2 * nb + 0], qfh[kc], khr + 0);
                mma16816(acc_s[2 * nb + 1], qfh[kc], khr + 2);
                mma16816(acc_s[2 * nb + 0], qfh[kc], klr + 0);
                mma16816(acc_s[2 * nb + 1], qfh[kc], klr + 2);
                mma16816(acc_s[2 * nb + 0], qfl[kc], khr + 0);
                mma16816(acc_s[2 * nb + 1], qfl[kc], khr + 2);
            }
        }

        // ---- warp-local online softmax (rows r=lane>>2 and r+8) ----
        float mx0 = -1e30f, mx1 = -1e30f;
#pragma unroll
        for (int j = 0; j < 8; j++) {
            mx0 = fmaxf(mx0, fmaxf(acc_s[j][0], acc_s[j][1]));
            mx1 = fmaxf(mx1, fmaxf(acc_s[j][2], acc_s[j][3]));
        }
        mx0 = fmaxf(mx0, __shfl_xor_sync(0xffffffffu, mx0, 1));
        mx0 = fmaxf(mx0, __shfl_xor_sync(0xffffffffu, mx0, 2));
        mx1 = fmaxf(mx1, __shfl_xor_sync(0xffffffffu, mx1, 1));
        mx1 = fmaxf(mx1, __shfl_xor_sync(0xffffffffu, mx1, 2));

        const float mn0 = fmaxf(m0, mx0);
        const float mn1 = fmaxf(m1, mx1);
        const float al0 = __expf(m0 - mn0);
        const float al1 = __expf(m1 - mn1);
        m0 = mn0; m1 = mn1;

#pragma unroll
        for (int j = 0; j < 8; j++) {
            acc_o[j][0] *= al0; acc_o[j][1] *= al0;
            acc_o[j][2] *= al1; acc_o[j][3] *= al1;
        }

        // ---- P in registers (exp + split) fused with PV MMAs ----
        float rs0 = 0.f, rs1 = 0.f;
#pragma unroll
        for (int f = 0; f < 4; f++) {
            const float e0 = __expf(acc_s[2 * f + 0][0] - mn0);
            const float e1 = __expf(acc_s[2 * f + 0][1] - mn0);
            const float e2 = __expf(acc_s[2 * f + 0][2] - mn1);
            const float e3 = __expf(acc_s[2 * f + 0][3] - mn1);
            const float e4 = __expf(acc_s[2 * f + 1][0] - mn0);
            const float e5 = __expf(acc_s[2 * f + 1][1] - mn0);
            const float e6 = __expf(acc_s[2 * f + 1][2] - mn1);
            const float e7 = __expf(acc_s[2 * f + 1][3] - mn1);
            rs0 += e0 + e1 + e4 + e5;
            rs1 += e2 + e3 + e6 + e7;

            const __nv_bfloat16 h0 = __float2bfloat16(e0);
            const __nv_bfloat16 h1 = __float2bfloat16(e1);
            const __nv_bfloat16 h2 = __float2bfloat16(e2);
            const __nv_bfloat16 h3 = __float2bfloat16(e3);
            const __nv_bfloat16 h4 = __float2bfloat16(e4);
            const __nv_bfloat16 h5 = __float2bfloat16(e5);
            const __nv_bfloat16 h6 = __float2bfloat16(e6);
            const __nv_bfloat16 h7 = __float2bfloat16(e7);
            uint32_t pa_h[4], pa_l[4];
            pa_h[0] = pk2(h0, h1);
            pa_h[1] = pk2(h2, h3);
            pa_h[2] = pk2(h4, h5);
            pa_h[3] = pk2(h6, h7);
            pa_l[0] = pk2(__float2bfloat16(e0 - __bfloat162float(h0)),
                          __float2bfloat16(e1 - __bfloat162float(h1)));
            pa_l[1] = pk2(__float2bfloat16(e2 - __bfloat162float(h2)),
                          __float2bfloat16(e3 - __bfloat162float(h3)));
            pa_l[2] = pk2(__float2bfloat16(e4 - __bfloat162float(h4)),
                          __float2bfloat16(e5 - __bfloat162float(h5)));
            pa_l[3] = pk2(__float2bfloat16(e6 - __bfloat162float(h6)),
                          __float2bfloat16(e7 - __bfloat162float(h7)));

#pragma unroll
            for (int db = 0; db < 4; db++) {
                const uint32_t vsw = SWZ((uint32_t)((f * 16 + v_kv) * 128 +
                                                    (v_d0 + db * 16) * 2));
                uint32_t vhr[4], vlr[4];
                ldsm_x4_t(vhr, VH + vsw);
                ldsm_x4_t(vlr, VL + vsw);
                mma16816(acc_o[2 * db + 0], pa_h, vhr + 0);
                mma16816(acc_o[2 * db + 1], pa_h, vhr + 2);
                mma16816(acc_o[2 * db + 0], pa_h, vlr + 0);
                mma16816(acc_o[2 * db + 1], pa_h, vlr + 2);
                mma16816(acc_o[2 * db + 0], pa_l, vhr + 0);
                mma16816(acc_o[2 * db + 1], pa_l, vhr + 2);
            }
        }
        rs0 += __shfl_xor_sync(0xffffffffu, rs0, 1);
        rs0 += __shfl_xor_sync(0xffffffffu, rs0, 2);
        rs1 += __shfl_xor_sync(0xffffffffu, rs1, 1);
        rs1 += __shfl_xor_sync(0xffffffffu, rs1, 2);
        l0 = l0 * al0 + rs0;
        l1 = l1 * al1 + rs1;
    }

    // ---- epilogue: normalize, split-bf16, store [B,S,H*D] ----
    const int b  = bh >> 4;
    const int hh = bh & 15;
    const float linv0 = 1.f / l0;
    const float linv1 = 1.f / l1;
    const int row0 = q0 + wm + (lane >> 2);
    const size_t ri0 = ((size_t)(b * SEQ + row0)) * DIM + hh * DPH;
    const size_t ri1 = ri0 + (size_t)8 * DIM;
#pragma unroll
    for (int j = 0; j < 8; j++) {
        const int d = j * 8 + (lane & 3) * 2;
        {
            const float v0 = acc_o[j][0] * linv0;
            const float v1 = acc_o[j][1] * linv0;
            const __nv_bfloat16 b0 = __float2bfloat16(v0);
            const __nv_bfloat16 b1 = __float2bfloat16(v1);
            *(uint32_t*)&outh[ri0 + d] = pk2(b0, b1);
            *(uint32_t*)&outl[ri0 + d] =
                pk2(__float2bfloat16(v0 - __bfloat162float(b0)),
                    __float2bfloat16(v1 - __bfloat162float(b1)));
        }
        {
            const float v0 = acc_o[j][2] * linv1;
            const float v1 = acc_o[j][3] * linv1;
            const __nv_bfloat16 b0 = __float2bfloat16(v0);
            const __nv_bfloat16 b1 = __float2bfloat16(v1);
            *(uint32_t*)&outh[ri1 + d] = pk2(b0, b1);
            *(uint32_t*)&outl[ri1 + d] =
                pk2(__float2bfloat16(v0 - __bfloat162float(b0)),
                    __float2bfloat16(v1 - __bfloat162float(b1)));
        }
    }
}
#undef AT2_LOADKV

// ---------------------------------------------------------------------------
// Launch
// ---------------------------------------------------------------------------
extern "C" void kernel_launch(void* const* d_in, const int* in_sizes, int n_in,
                              void* d_out, int out_size)
{
    const float* query = (const float*)d_in[0];
    const float* key   = (const float*)d_in[1];
    const float* value = (const float*)d_in[2];
    const float* Wq    = (const float*)d_in[4];
    const float* bq    = (const float*)d_in[5];
    const float* Wk    = (const float*)d_in[6];
    const float* bk    = (const float*)d_in[7];
    const float* Wv    = (const float*)d_in[8];
    const float* bv    = (const float*)d_in[9];
    const float* Wo    = (const float*)d_in[10];
    const float* bo    = (const float*)d_in[11];
    float* out = (float*)d_out;

    __nv_bfloat16 *ahp, *alp, *whp, *wlp, *qhp, *qlp, *khp, *klp, *vhp, *vlp;
    cudaGetSymbolAddress((void**)&ahp, g_ah);
    cudaGetSymbolAddress((void**)&alp, g_al);
    cudaGetSymbolAddress((void**)&whp, g_wh);
    cudaGetSymbolAddress((void**)&wlp, g_wl);
    cudaGetSymbolAddress((void**)&qhp, g_qh);
    cudaGetSymbolAddress((void**)&qlp, g_ql);
    cudaGetSymbolAddress((void**)&khp, g_kh);
    cudaGetSymbolAddress((void**)&klp, g_kl);
    cudaGetSymbolAddress((void**)&vhp, g_vh);
    cudaGetSymbolAddress((void**)&vlp, g_vl);

    cudaFuncSetAttribute(gemm_tc, cudaFuncAttributeMaxDynamicSharedMemorySize,
                         GT_SMEM_TOTAL);
    cudaFuncSetAttribute(attn_tc, cudaFuncAttributeMaxDynamicSharedMemorySize,
                         AT2_SMEM);

    const int nA4 = M_TOT * DIM / 4;
    const int nW4 = DIM * DIM / 4;
    const dim3 ggrid(DIM / 128, M_TOT / 128);   // (8, 64)

    // Q projection: fp32 in -> split-bf16 Q (scale 0.125 folded in)
    split_bf16<<<nA4 / 256, 256>>>(query, ahp, alp, nA4);
    split_bf16<<<nW4 / 256, 256>>>(Wq, whp, wlp, nW4);
    gemm_tc<<<ggrid, 256, GT_SMEM_TOTAL>>>(ahp, alp, whp, wlp, bq,
                                           nullptr, qhp, qlp, 0.125f, 1);

    // K projection
    split_bf16<<<nA4 / 256, 256>>>(key, ahp, alp, nA4);
    split_bf16<<<nW4 / 256, 256>>>(Wk, whp, wlp, nW4);
    gemm_tc<<<ggrid, 256, GT_SMEM_TOTAL>>>(ahp, alp, whp, wlp, bk,
                                           nullptr, khp, klp, 1.0f, 1);

    // V projection
    split_bf16<<<nA4 / 256, 256>>>(value, ahp, alp, nA4);
    split_bf16<<<nW4 / 256, 256>>>(Wv, whp, wlp, nW4);
    gemm_tc<<<ggrid, 256, GT_SMEM_TOTAL>>>(ahp, alp, whp, wlp, bv,
                                           nullptr, vhp, vlp, 1.0f, 1);

    // Attention: writes split-bf16 context straight into (g_ah, g_al)
    attn_tc<<<dim3(SEQ / 128, BS * NH), 256, AT2_SMEM>>>(
        qhp, qlp, khp, klp, vhp, vlp, ahp, alp);

    // Output projection -> fp32 d_out
    split_bf16<<<nW4 / 256, 256>>>(Wo, whp, wlp, nW4);
    gemm_tc<<<ggrid, 256, GT_SMEM_TOTAL>>>(ahp, alp, whp, wlp, bo,
                                           out, nullptr, nullptr, 1.0f, 0);
}

// round 17
// speedup vs baseline: 1.5284x; 1.5284x over previous
#include <cuda_runtime.h>
#include <cuda_bf16.h>
#include <math.h>
#include <stdint.h>

// Problem constants
#define BS   4
#define SEQ  2048
#define DIM  1024
#define NH   16
#define DPH  64
#define M_TOT (BS * SEQ)   // 8192

// ---------------------------------------------------------------------------
// Scratch (device globals)
// ---------------------------------------------------------------------------
__device__ __nv_bfloat16 g_ah[(size_t)M_TOT * DIM];
__device__ __nv_bfloat16 g_al[(size_t)M_TOT * DIM];
__device__ __nv_bfloat16 g_wh[(size_t)DIM * DIM];
__device__ __nv_bfloat16 g_wl[(size_t)DIM * DIM];
__device__ __nv_bfloat16 g_qh[(size_t)M_TOT * DIM];
__device__ __nv_bfloat16 g_ql[(size_t)M_TOT * DIM];
__device__ __nv_bfloat16 g_kh[(size_t)M_TOT * DIM];
__device__ __nv_bfloat16 g_kl[(size_t)M_TOT * DIM];
__device__ __nv_bfloat16 g_vh[(size_t)M_TOT * DIM];
__device__ __nv_bfloat16 g_vl[(size_t)M_TOT * DIM];

// ---------------------------------------------------------------------------
// fp32 -> (bf16 hi, bf16 lo) split
// ---------------------------------------------------------------------------
__global__ void __launch_bounds__(256)
split_bf16(const float* __restrict__ x, __nv_bfloat16* __restrict__ hi,
           __nv_bfloat16* __restrict__ lo, int n4)
{
    int i = blockIdx.x * blockDim.x + threadIdx.x;
    if (i >= n4) return;
    float4 v = ((const float4*)x)[i];
    __nv_bfloat16 h0 = __float2bfloat16(v.x);
    __nv_bfloat16 h1 = __float2bfloat16(v.y);
    __nv_bfloat16 h2 = __float2bfloat16(v.z);
    __nv_bfloat16 h3 = __float2bfloat16(v.w);
    __nv_bfloat16 l0 = __float2bfloat16(v.x - __bfloat162float(h0));
    __nv_bfloat16 l1 = __float2bfloat16(v.y - __bfloat162float(h1));
    __nv_bfloat16 l2 = __float2bfloat16(v.z - __bfloat162float(h2));
    __nv_bfloat16 l3 = __float2bfloat16(v.w - __bfloat162float(h3));
    ushort4 hu = make_ushort4(__bfloat16_as_ushort(h0), __bfloat16_as_ushort(h1),
                              __bfloat16_as_ushort(h2), __bfloat16_as_ushort(h3));
    ushort4 lu = make_ushort4(__bfloat16_as_ushort(l0), __bfloat16_as_ushort(l1),
                              __bfloat16_as_ushort(l2), __bfloat16_as_ushort(l3));
    ((ushort4*)hi)[i] = hu;
    ((ushort4*)lo)[i] = lu;
}

// ---------------------------------------------------------------------------
// mma.sync / ldmatrix helpers (sm_80-level PTX)
// ---------------------------------------------------------------------------
static __device__ __forceinline__ uint32_t smem_u32(const void* p) {
    uint32_t a;
    asm("{ .reg .u64 t; cvta.to.shared.u64 t, %1; cvt.u32.u64 %0, t; }"
        : "=r"(a) : "l"(p));
    return a;
}

__device__ __forceinline__ void cp16(uint32_t dst, const void* src) {
    asm volatile("cp.async.cg.shared.global [%0], [%1], 16;" :: "r"(dst), "l"(src));
}
__device__ __forceinline__ void cp_commit() {
    asm volatile("cp.async.commit_group;" ::: "memory");
}
__device__ __forceinline__ void cp_wait1() {
    asm volatile("cp.async.wait_group 1;" ::: "memory");
}
__device__ __forceinline__ void cp_wait0() {
    asm volatile("cp.async.wait_group 0;" ::: "memory");
}

__device__ __forceinline__ void ldsm_x4(uint32_t* r, uint32_t addr) {
    asm volatile("ldmatrix.sync.aligned.m8n8.x4.shared.b16 {%0,%1,%2,%3}, [%4];"
                 : "=r"(r[0]), "=r"(r[1]), "=r"(r[2]), "=r"(r[3]) : "r"(addr));
}
__device__ __forceinline__ void ldsm_x4_t(uint32_t* r, uint32_t addr) {
    asm volatile("ldmatrix.sync.aligned.m8n8.x4.trans.shared.b16 {%0,%1,%2,%3}, [%4];"
                 : "=r"(r[0]), "=r"(r[1]), "=r"(r[2]), "=r"(r[3]) : "r"(addr));
}

__device__ __forceinline__ void mma16816(float* c, const uint32_t* a,
                                         const uint32_t* b) {
    asm volatile(
        "mma.sync.aligned.m16n8k16.row.col.f32.bf16.bf16.f32 "
        "{%0,%1,%2,%3}, {%4,%5,%6,%7}, {%8,%9}, {%0,%1,%2,%3};"
        : "+f"(c[0]), "+f"(c[1]), "+f"(c[2]), "+f"(c[3])
        : "r"(a[0]), "r"(a[1]), "r"(a[2]), "r"(a[3]), "r"(b[0]), "r"(b[1]));
}

__device__ __forceinline__ uint32_t pk2(__nv_bfloat16 a, __nv_bfloat16 b) {
    return (uint32_t)__bfloat16_as_ushort(a) |
           ((uint32_t)__bfloat16_as_ushort(b) << 16);
}

// SW128 swizzle of a byte offset within a 128B-pitch tile
#define SWZ(o) ((o) ^ (((o) >> 3) & 0x70))

// ---------------------------------------------------------------------------
// HMMA split-bf16 GEMM (unchanged from R10 — validated)
// ---------------------------------------------------------------------------
#define GT_STAGE_BYTES 65536
#define GT_OFF_AH 0
#define GT_OFF_AL 16384
#define GT_OFF_WH 32768
#define GT_OFF_WL 49152
#define GT_SMEM_TOTAL (2 * GT_STAGE_BYTES)

__global__ void __launch_bounds__(256)
gemm_tc(const __nv_bfloat16* __restrict__ ah, const __nv_bfloat16* __restrict__ al,
        const __nv_bfloat16* __restrict__ wh, const __nv_bfloat16* __restrict__ wl,
        const float* __restrict__ bias, float* __restrict__ Cf,
        __nv_bfloat16* __restrict__ Ch, __nv_bfloat16* __restrict__ Cl,
        float scale, int mode)
{
    extern __shared__ char smc[];
    const uint32_t sb = smem_u32(smc);
    const int tid  = threadIdx.x;
    const int wid  = tid >> 5;
    const int lane = tid & 31;
    const int m0 = blockIdx.y << 7;
    const int n0 = blockIdx.x << 7;

    const int wm = (wid & 3) * 32;
    const int wn = (wid >> 2) * 64;

    const int r0  = tid >> 3;
    const int seg = tid & 7;
    const __nv_bfloat16* aph = ah + (size_t)(m0 + r0) * DIM + seg * 8;
    const __nv_bfloat16* apl = al + (size_t)(m0 + r0) * DIM + seg * 8;
    const __nv_bfloat16* wph = wh + (size_t)(n0 + r0) * DIM + seg * 8;
    const __nv_bfloat16* wpl = wl + (size_t)(n0 + r0) * DIM + seg * 8;

#define LOAD_CHUNK(chunk, s)                                                   \
    do {                                                                       \
        const uint32_t buf = sb + (s) * GT_STAGE_BYTES;                        \
        const size_t koff = (size_t)(chunk) * 64;                              \
        _Pragma("unroll")                                                      \
        for (int i_ = 0; i_ < 4; i_++) {                                       \
            const uint32_t sw = SWZ((uint32_t)((r0 + 32 * i_) * 128 + seg * 16)); \
            const size_t ro = (size_t)(32 * i_) * DIM + koff;                  \
            cp16(buf + GT_OFF_AH + sw, aph + ro);                              \
            cp16(buf + GT_OFF_AL + sw, apl + ro);                              \
            cp16(buf + GT_OFF_WH + sw, wph + ro);                              \
            cp16(buf + GT_OFF_WL + sw, wpl + ro);                              \
        }                                                                      \
        cp_commit();                                                           \
    } while (0)

    const int a_row   = wm + (lane & 15);
    const int a_half  = (lane >> 4) << 4;
    const uint32_t a_xor   = (uint32_t)((a_row & 7) << 4);
    const uint32_t a_roff0 = (uint32_t)(a_row * 128);
    const uint32_t a_roff1 = a_roff0 + 16 * 128;

    const int b_row  = wn + (lane & 7) + ((lane & 16) >> 1);
    const int b_half = (lane & 8) ? 16 : 0;
    const uint32_t b_xor  = (uint32_t)((b_row & 7) << 4);
    const uint32_t b_roff = (uint32_t)(b_row * 128);

    float acc[2][8][4];
#pragma unroll
    for (int i = 0; i < 2; i++)
#pragma unroll
        for (int j = 0; j < 8; j++)
#pragma unroll
            for (int t = 0; t < 4; t++) acc[i][j][t] = 0.f;

    LOAD_CHUNK(0, 0);
    LOAD_CHUNK(1, 1);

    for (int c = 0; c < 16; c++) {
        const int s = c & 1;
        if (c < 15) cp_wait1(); else cp_wait0();
        __syncthreads();

        const uint32_t buf = sb + s * GT_STAGE_BYTES;
        const uint32_t tah = buf + GT_OFF_AH;
        const uint32_t tal = buf + GT_OFF_AL;
        const uint32_t twh = buf + GT_OFF_WH;
        const uint32_t twl = buf + GT_OFF_WL;

#pragma unroll
        for (int kc = 0; kc < 4; kc++) {
            const uint32_t abyte = (uint32_t)(a_half + kc * 32) ^ a_xor;
            uint32_t ah0[4], ah1[4], al0[4], al1[4];
            ldsm_x4(ah0, tah + a_roff0 + abyte);
            ldsm_x4(ah1, tah + a_roff1 + abyte);
            ldsm_x4(al0, tal + a_roff0 + abyte);
            ldsm_x4(al1, tal + a_roff1 + abyte);

            const uint32_t bbyte = (uint32_t)(b_half + kc * 32) ^ b_xor;
#pragma unroll
            for (int nb = 0; nb < 4; nb++) {
                uint32_t bh[4], bl[4];
                const uint32_t bro = b_roff + (uint32_t)(nb * 16 * 128);
                ldsm_x4(bh, twh + bro + bbyte);
                ldsm_x4(bl, twl + bro + bbyte);
                mma16816(acc[0][2 * nb + 0], ah0, bh + 0);
                mma16816(acc[0][2 * nb + 1], ah0, bh + 2);
                mma16816(acc[1][2 * nb + 0], ah1, bh + 0);
                mma16816(acc[1][2 * nb + 1], ah1, bh + 2);
                mma16816(acc[0][2 * nb + 0], ah0, bl + 0);
                mma16816(acc[0][2 * nb + 1], ah0, bl + 2);
                mma16816(acc[1][2 * nb + 0], ah1, bl + 0);
                mma16816(acc[1][2 * nb + 1], ah1, bl + 2);
                mma16816(acc[0][2 * nb + 0], al0, bh + 0);
                mma16816(acc[0][2 * nb + 1], al0, bh + 2);
                mma16816(acc[1][2 * nb + 0], al1, bh + 0);
                mma16816(acc[1][2 * nb + 1], al1, bh + 2);
            }
        }

        __syncthreads();
        if (c + 2 < 16) LOAD_CHUNK(c + 2, s);
    }

    const int erow = lane >> 2;
    const int ecol = (lane & 3) * 2;
#pragma unroll
    for (int mi = 0; mi < 2; mi++) {
#pragma unroll
        for (int half = 0; half < 2; half++) {
            const int m = m0 + wm + mi * 16 + erow + half * 8;
            const int b = m >> 11;
            const int sx = m & 2047;
#pragma unroll
            for (int ni = 0; ni < 8; ni++) {
                const int n = n0 + wn + ni * 8 + ecol;
                const float2 bv = __ldg((const float2*)(bias + n));
                float2 v;
                v.x = (acc[mi][ni][2 * half + 0] + bv.x) * scale;
                v.y = (acc[mi][ni][2 * half + 1] + bv.y) * scale;
                if (mode == 0) {
                    *(float2*)&Cf[(size_t)m * DIM + n] = v;
                } else {
                    const int h = n >> 6;
                    const int d = n & 63;
                    const size_t idx =
                        ((size_t)((b << 4) + h) * SEQ + sx) * DPH + d;
                    __nv_bfloat16 hx = __float2bfloat16(v.x);
                    __nv_bfloat16 hy = __float2bfloat16(v.y);
                    *(uint32_t*)&Ch[idx] = pk2(hx, hy);
                    *(uint32_t*)&Cl[idx] =
                        pk2(__float2bfloat16(v.x - __bfloat162float(hx)),
                            __float2bfloat16(v.y - __bfloat162float(hy)));
                }
            }
        }
    }
}
#undef LOAD_CHUNK

// ---------------------------------------------------------------------------
// HMMA split-bf16 flash attention, FA2-style:
//  - 8 warps x 16 q-rows (M-only partition): softmax is warp-local (quad shfl)
//  - P stays in registers (S c-frag pairs == P a-frags), no smem round-trip
//  - Q in registers after one-time ldmatrix
//  - 3-stage cp.async KV pipeline, ONE __syncthreads per kv chunk
// ---------------------------------------------------------------------------
#define AT2_QH 0
#define AT2_QL 16384
#define AT2_STAGE(s) (32768 + (s) * 32768)   // KH+0, KL+8192, VH+16384, VL+24576
#define AT2_SMEM (32768 + 3 * 32768)          // 131072 bytes

__global__ void __launch_bounds__(256)
attn_tc(const __nv_bfloat16* __restrict__ qh, const __nv_bfloat16* __restrict__ ql,
        const __nv_bfloat16* __restrict__ kh, const __nv_bfloat16* __restrict__ kl,
        const __nv_bfloat16* __restrict__ vh, const __nv_bfloat16* __restrict__ vl,
        __nv_bfloat16* __restrict__ outh, __nv_bfloat16* __restrict__ outl)
{
    extern __shared__ char smc[];
    const uint32_t sb = smem_u32(smc);
    const int tid  = threadIdx.x;
    const int wid  = tid >> 5;
    const int lane = tid & 31;
    const int wm = wid * 16;                  // warp's 16 q-rows
    const int bh = blockIdx.y;
    const int q0 = blockIdx.x << 7;
    const size_t base = (size_t)bh * SEQ * DPH;

    // ---- cp.async pointers ----
    const int r0  = tid >> 3;   // 0..31
    const int seg = tid & 7;    // 0..7
    const __nv_bfloat16* qhg = qh + base + (size_t)(q0 + r0) * DPH + seg * 8;
    const __nv_bfloat16* qlg = ql + base + (size_t)(q0 + r0) * DPH + seg * 8;
    const __nv_bfloat16* khg = kh + base + (size_t)r0 * DPH + seg * 8;
    const __nv_bfloat16* klg = kl + base + (size_t)r0 * DPH + seg * 8;
    const __nv_bfloat16* vhg = vh + base + (size_t)r0 * DPH + seg * 8;
    const __nv_bfloat16* vlg = vl + base + (size_t)r0 * DPH + seg * 8;
    const uint32_t ldsw = SWZ((uint32_t)(r0 * 128 + seg * 16));
    const uint32_t ldsw2 = SWZ((uint32_t)((r0 + 32) * 128 + seg * 16));

#define AT2_LOADKV(chunk, s)                                                   \
    do {                                                                       \
        const uint32_t st = sb + AT2_STAGE(s);                                 \
        const size_t co = (size_t)(chunk) * 64 * DPH;                          \
        cp16(st + ldsw,          khg + co);                                    \
        cp16(st + ldsw2,         khg + co + 32 * DPH);                         \
        cp16(st + 8192  + ldsw,  klg + co);                                    \
        cp16(st + 8192  + ldsw2, klg + co + 32 * DPH);                         \
        cp16(st + 16384 + ldsw,  vhg + co);                                    \
        cp16(st + 16384 + ldsw2, vhg + co + 32 * DPH);                         \
        cp16(st + 24576 + ldsw,  vlg + co);                                    \
        cp16(st + 24576 + ldsw2, vlg + co + 32 * DPH);                         \
    } while (0)

    // prologue: group 0 = Q + chunk 0; group 1 = chunk 1
#pragma unroll
    for (int i = 0; i < 4; i++) {
        const uint32_t sw = SWZ((uint32_t)((r0 + 32 * i) * 128 + seg * 16));
        cp16(sb + AT2_QH + sw, qhg + (size_t)(32 * i) * DPH);
        cp16(sb + AT2_QL + sw, qlg + (size_t)(32 * i) * DPH);
    }
    AT2_LOADKV(0, 0);
    cp_commit();
    AT2_LOADKV(1, 1);
    cp_commit();

    // ---- ldmatrix lane addressing ----
    const int a_row = wm + (lane & 15);
    const uint32_t a_xor  = (uint32_t)((a_row & 7) << 4);
    const uint32_t a_off  = (uint32_t)(a_row * 128);
    const uint32_t a_half = (uint32_t)((lane >> 4) << 4);

    const int b_rb = (lane & 7) + ((lane & 16) >> 1);       // row within n16 blk
    const uint32_t b_xor  = (uint32_t)((b_rb & 7) << 4);
    const uint32_t b_half = (lane & 8) ? 16u : 0u;

    const int v_kv = lane & 15;
    const int v_d0 = (lane >> 4) << 3;

    // ---- persistent registers ----
    uint32_t qfh[4][4], qfl[4][4];
    float acc_o[8][4];
#pragma unroll
    for (int j = 0; j < 8; j++)
#pragma unroll
        for (int t = 0; t < 4; t++) acc_o[j][t] = 0.f;
    float m0 = -1e30f, m1 = -1e30f, l0 = 0.f, l1 = 0.f;

    for (int c = 0; c < 32; c++) {
        const int s = c - (c / 3) * 3;   // c % 3
        if (c < 31) cp_wait1(); else cp_wait0();
        __syncthreads();

        if (c == 0) {
            // one-time Q -> registers
#pragma unroll
            for (int kc = 0; kc < 4; kc++) {
                const uint32_t ab = (uint32_t)(a_half + kc * 32) ^ a_xor;
                ldsm_x4(qfh[kc], sb + AT2_QH + a_off + ab);
                ldsm_x4(qfl[kc], sb + AT2_QL + a_off + ab);
            }
        }
        if (c < 30) {   // prefetch chunk c+2 into buffer vacated at c-1
            const int s2 = (c + 2) - ((c + 2) / 3) * 3;
            AT2_LOADKV(c + 2, s2);
            cp_commit();
        }

        const uint32_t KH = sb + AT2_STAGE(s);
        const uint32_t KL = KH + 8192;
        const uint32_t VH = KH + 16384;
        const uint32_t VL = KH + 24576;

        // ---- S = Q K^T (3 split terms), 16 x 64 per warp ----
        float acc_s[8][4];
#pragma unroll
        for (int j = 0; j < 8; j++)
#pragma unroll
            for (int t = 0; t < 4; t++) acc_s[j][t] = 0.f;

#pragma unroll
        for (int kc = 0; kc < 4; kc++) {
            const uint32_t bb = (uint32_t)(b_half + kc * 32) ^ b_xor;
#pragma unroll
            for (int nb = 0; nb < 4; nb++) {
                const uint32_t bro = (uint32_t)((nb * 16 + b_rb) * 128);
                uint32_t khr[4], klr[4];
                ldsm_x4(khr, KH + bro + bb);
                ldsm_x4(klr, KL + bro + bb);
                mma16816(acc_s[2 * nb + 0], qfh[kc], khr + 0);
                mma16816(acc_s[2 * nb + 1], qfh[kc], khr + 2);
                mma16816(acc_s[2 * nb + 0], qfh[kc], klr + 0);
                mma16816(acc_s[2 * nb + 1], qfh[kc], klr + 2);
                mma16816(acc_s[2 * nb + 0], qfl[kc], khr + 0);
                mma16816(acc_s[2 * nb + 1], qfl[kc], khr + 2);
            }
        }

        // ---- warp-local online softmax (rows r=lane>>2 and r+8) ----
        float mx0 = -1e30f, mx1 = -1e30f;
#pragma unroll
        for (int j = 0; j < 8; j++) {
            mx0 = fmaxf(mx0, fmaxf(acc_s[j][0], acc_s[j][1]));
            mx1 = fmaxf(mx1, fmaxf(acc_s[j][2], acc_s[j][3]));
        }
        mx0 = fmaxf(mx0, __shfl_xor_sync(0xffffffffu, mx0, 1));
        mx0 = fmaxf(mx0, __shfl_xor_sync(0xffffffffu, mx0, 2));
        mx1 = fmaxf(mx1, __shfl_xor_sync(0xffffffffu, mx1, 1));
        mx1 = fmaxf(mx1, __shfl_xor_sync(0xffffffffu, mx1, 2));

        const float mn0 = fmaxf(m0, mx0);
        const float mn1 = fmaxf(m1, mx1);
        const float al0 = __expf(m0 - mn0);
        const float al1 = __expf(m1 - mn1);
        m0 = mn0; m1 = mn1;

#pragma unroll
        for (int j = 0; j < 8; j++) {
            acc_o[j][0] *= al0; acc_o[j][1] *= al0;
            acc_o[j][2] *= al1; acc_o[j][3] *= al1;
        }

        // ---- P in registers (exp + split) fused with PV MMAs ----
        float rs0 = 0.f, rs1 = 0.f;
#pragma unroll
        for (int f = 0; f < 4; f++) {
            const float e0 = __expf(acc_s[2 * f + 0][0] - mn0);
            const float e1 = __expf(acc_s[2 * f + 0][1] - mn0);
            const float e2 = __expf(acc_s[2 * f + 0][2] - mn1);
            const float e3 = __expf(acc_s[2 * f + 0][3] - mn1);
            const float e4 = __expf(acc_s[2 * f + 1][0] - mn0);
            const float e5 = __expf(acc_s[2 * f + 1][1] - mn0);
            const float e6 = __expf(acc_s[2 * f + 1][2] - mn1);
            const float e7 = __expf(acc_s[2 * f + 1][3] - mn1);
            rs0 += e0 + e1 + e4 + e5;
            rs1 += e2 + e3 + e6 + e7;

            const __nv_bfloat16 h0 = __float2bfloat16(e0);
            const __nv_bfloat16 h1 = __float2bfloat16(e1);
            const __nv_bfloat16 h2 = __float2bfloat16(e2);
            const __nv_bfloat16 h3 = __float2bfloat16(e3);
            const __nv_bfloat16 h4 = __float2bfloat16(e4);
            const __nv_bfloat16 h5 = __float2bfloat16(e5);
            const __nv_bfloat16 h6 = __float2bfloat16(e6);
            const __nv_bfloat16 h7 = __float2bfloat16(e7);
            uint32_t pa_h[4], pa_l[4];
            pa_h[0] = pk2(h0, h1);
            pa_h[1] = pk2(h2, h3);
            pa_h[2] = pk2(h4, h5);
            pa_h[3] = pk2(h6, h7);
            pa_l[0] = pk2(__float2bfloat16(e0 - __bfloat162float(h0)),
                          __float2bfloat16(e1 - __bfloat162float(h1)));
            pa_l[1] = pk2(__float2bfloat16(e2 - __bfloat162float(h2)),
                          __float2bfloat16(e3 - __bfloat162float(h3)));
            pa_l[2] = pk2(__float2bfloat16(e4 - __bfloat162float(h4)),
                          __float2bfloat16(e5 - __bfloat162float(h5)));
            pa_l[3] = pk2(__float2bfloat16(e6 - __bfloat162float(h6)),
                          __float2bfloat16(e7 - __bfloat162float(h7)));

#pragma unroll
            for (int db = 0; db < 4; db++) {
                const uint32_t vsw = SWZ((uint32_t)((f * 16 + v_kv) * 128 +
                                                    (v_d0 + db * 16) * 2));
                uint32_t vhr[4], vlr[4];
                ldsm_x4_t(vhr, VH + vsw);
                ldsm_x4_t(vlr, VL + vsw);
                mma16816(acc_o[2 * db + 0], pa_h, vhr + 0);
                mma16816(acc_o[2 * db + 1], pa_h, vhr + 2);
                mma16816(acc_o[2 * db + 0], pa_h, vlr + 0);
                mma16816(acc_o[2 * db + 1], pa_h, vlr + 2);
                mma16816(acc_o[2 * db + 0], pa_l, vhr + 0);
                mma16816(acc_o[2 * db + 1], pa_l, vhr + 2);
            }
        }
        rs0 += __shfl_xor_sync(0xffffffffu, rs0, 1);
        rs0 += __shfl_xor_sync(0xffffffffu, rs0, 2);
        rs1 += __shfl_xor_sync(0xffffffffu, rs1, 1);
        rs1 += __shfl_xor_sync(0xffffffffu, rs1, 2);
        l0 = l0 * al0 + rs0;
        l1 = l1 * al1 + rs1;
    }

    // ---- epilogue: normalize, split-bf16, store [B,S,H*D] ----
    const int b  = bh >> 4;
    const int hh = bh & 15;
    const float linv0 = 1.f / l0;
    const float linv1 = 1.f / l1;
    const int row0 = q0 + wm + (lane >> 2);
    const size_t ri0 = ((size_t)(b * SEQ + row0)) * DIM + hh * DPH;
    const size_t ri1 = ri0 + (size_t)8 * DIM;
#pragma unroll
    for (int j = 0; j < 8; j++) {
        const int d = j * 8 + (lane & 3) * 2;
        {
            const float v0 = acc_o[j][0] * linv0;
            const float v1 = acc_o[j][1] * linv0;
            const __nv_bfloat16 b0 = __float2bfloat16(v0);
            const __nv_bfloat16 b1 = __float2bfloat16(v1);
            *(uint32_t*)&outh[ri0 + d] = pk2(b0, b1);
            *(uint32_t*)&outl[ri0 + d] =
                pk2(__float2bfloat16(v0 - __bfloat162float(b0)),
                    __float2bfloat16(v1 - __bfloat162float(b1)));
        }
        {
            const float v0 = acc_o[j][2] * linv1;
            const float v1 = acc_o[j][3] * linv1;
            const __nv_bfloat16 b0 = __float2bfloat16(v0);
            const __nv_bfloat16 b1 = __float2bfloat16(v1);
            *(uint32_t*)&outh[ri1 + d] = pk2(b0, b1);
            *(uint32_t*)&outl[ri1 + d] =
                pk2(__float2bfloat16(v0 - __bfloat162float(b0)),
                    __float2bfloat16(v1 - __bfloat162float(b1)));
        }
    }
}
#undef AT2_LOADKV

// ---------------------------------------------------------------------------
// Launch
// ---------------------------------------------------------------------------
extern "C" void kernel_launch(void* const* d_in, const int* in_sizes, int n_in,
                              void* d_out, int out_size)
{
    const float* query = (const float*)d_in[0];
    const float* key   = (const float*)d_in[1];
    const float* value = (const float*)d_in[2];
    const float* Wq    = (const float*)d_in[4];
    const float* bq    = (const float*)d_in[5];
    const float* Wk    = (const float*)d_in[6];
    const float* bk    = (const float*)d_in[7];
    const float* Wv    = (const float*)d_in[8];
    const float* bv    = (const float*)d_in[9];
    const float* Wo    = (const float*)d_in[10];
    const float* bo    = (const float*)d_in[11];
    float* out = (float*)d_out;

    __nv_bfloat16 *ahp, *alp, *whp, *wlp, *qhp, *qlp, *khp, *klp, *vhp, *vlp;
    cudaGetSymbolAddress((void**)&ahp, g_ah);
    cudaGetSymbolAddress((void**)&alp, g_al);
    cudaGetSymbolAddress((void**)&whp, g_wh);
    cudaGetSymbolAddress((void**)&wlp, g_wl);
    cudaGetSymbolAddress((void**)&qhp, g_qh);
    cudaGetSymbolAddress((void**)&qlp, g_ql);
    cudaGetSymbolAddress((void**)&khp, g_kh);
    cudaGetSymbolAddress((void**)&klp, g_kl);
    cudaGetSymbolAddress((void**)&vhp, g_vh);
    cudaGetSymbolAddress((void**)&vlp, g_vl);

    cudaFuncSetAttribute(gemm_tc, cudaFuncAttributeMaxDynamicSharedMemorySize,
                         GT_SMEM_TOTAL);
    cudaFuncSetAttribute(attn_tc, cudaFuncAttributeMaxDynamicSharedMemorySize,
                         AT2_SMEM);

    const int nA4 = M_TOT * DIM / 4;
    const int nW4 = DIM * DIM / 4;
    const dim3 ggrid(DIM / 128, M_TOT / 128);   // (8, 64)

    // Q projection: fp32 in -> split-bf16 Q (scale 0.125 folded in)
    split_bf16<<<nA4 / 256, 256>>>(query, ahp, alp, nA4);
    split_bf16<<<nW4 / 256, 256>>>(Wq, whp, wlp, nW4);
    gemm_tc<<<ggrid, 256, GT_SMEM_TOTAL>>>(ahp, alp, whp, wlp, bq,
                                           nullptr, qhp, qlp, 0.125f, 1);

    // K projection
    split_bf16<<<nA4 / 256, 256>>>(key, ahp, alp, nA4);
    split_bf16<<<nW4 / 256, 256>>>(Wk, whp, wlp, nW4);
    gemm_tc<<<ggrid, 256, GT_SMEM_TOTAL>>>(ahp, alp, whp, wlp, bk,
                                           nullptr, khp, klp, 1.0f, 1);

    // V projection
    split_bf16<<<nA4 / 256, 256>>>(value, ahp, alp, nA4);
    split_bf16<<<nW4 / 256, 256>>>(Wv, whp, wlp, nW4);
    gemm_tc<<<ggrid, 256, GT_SMEM_TOTAL>>>(ahp, alp, whp, wlp, bv,
                                           nullptr, vhp, vlp, 1.0f, 1);

    // Attention: writes split-bf16 context straight into (g_ah, g_al)
    attn_tc<<<dim3(SEQ / 128, BS * NH), 256, AT2_SMEM>>>(
        qhp, qlp, khp, klp, vhp, vlp, ahp, alp);

    // Output projection -> fp32 d_out
    split_bf16<<<nW4 / 256, 256>>>(Wo, whp, wlp, nW4);
    gemm_tc<<<ggrid, 256, GT_SMEM_TOTAL>>>(ahp, alp, whp, wlp, bo,
                                           out, nullptr, nullptr, 1.0f, 0);
}